// round 1
// baseline (speedup 1.0000x reference)
#include <cuda_runtime.h>
#include <cstddef>

#define HID   256
#define NMSG  200001
#define NNODE 100000
#define MPAD  200064   // NMSG rounded up to multiple of 128
#define NTREE 512

// ---------------- scratch (device globals: no allocation allowed) ----------
__device__ float g_h   [(size_t)MPAD * HID];
__device__ float g_hUr [(size_t)MPAD * HID];
__device__ float g_r1  [(size_t)MPAD * HID];   // x@Wr + bUr
__device__ float g_xWz [(size_t)MPAD * HID];   // x@Wz_top + bz
__device__ float g_xWh [(size_t)MPAD * HID];   // x@Wh_top + bh
__device__ float g_sumh[(size_t)MPAD * HID];
__device__ float g_sg  [(size_t)MPAD * HID];

__device__ __forceinline__ float fsigmoid(float x) {
    return 1.0f / (1.0f + __expf(-x));
}
__device__ __forceinline__ float ftanh(float x) {
    x = fminf(fmaxf(x, -15.0f), 15.0f);
    float e = __expf(2.0f * x);
    return (e - 1.0f) / (e + 1.0f);
}

// ---------------------------------------------------------------------------
// Single GEMM: C[M x 256] = A[M x 256] @ B[256 x 256] (+ bias)
// Optional A-gather: A row r = emb[fnode[fmess[r]]]   (prologue)
// Tiling: BM=128, BN=64, BK=16, 256 threads, 8x4 per thread.
// ---------------------------------------------------------------------------
__global__ void __launch_bounds__(256)
gemm_single(const float* __restrict__ A,
            const float* __restrict__ B,
            const float* __restrict__ bias,
            float* __restrict__ C,
            const int* __restrict__ fmess,
            const int* __restrict__ fnode,
            const float* __restrict__ emb,
            int gather)
{
    __shared__ float As[16][132];   // [k][m], padded
    __shared__ float Bs[16][68];    // [k][n], padded

    const int m0  = blockIdx.x * 128;
    const int n0  = blockIdx.y * 64;
    const int tid = threadIdx.x;
    const int ty  = tid >> 4;        // 0..15 -> rows ty*8..ty*8+7
    const int tx  = tid & 15;        // 0..15 -> cols tx*4..tx*4+3

    // Hoist A row pointers (row index per load slot is k-invariant)
    const float* aptr[2];
    bool aval[2];
#pragma unroll
    for (int l = 0; l < 2; l++) {
        int L   = tid + l * 256;
        int r   = L >> 2;
        int row = m0 + r;
        aval[l] = (row < NMSG);
        if (aval[l]) {
            if (gather) {
                int src = fnode[fmess[row]];
                aptr[l] = emb + (size_t)src * HID;
            } else {
                aptr[l] = A + (size_t)row * HID;
            }
        } else {
            aptr[l] = emb; // dummy, never loaded
        }
    }

    float acc[8][4];
#pragma unroll
    for (int i = 0; i < 8; i++)
#pragma unroll
        for (int j = 0; j < 4; j++) acc[i][j] = 0.0f;

    for (int k0 = 0; k0 < HID; k0 += 16) {
        // load A tile (transposed into smem)
#pragma unroll
        for (int l = 0; l < 2; l++) {
            int L  = tid + l * 256;
            int r  = L >> 2;
            int k4 = (L & 3) * 4;
            float4 v = make_float4(0.f, 0.f, 0.f, 0.f);
            if (aval[l]) v = *(const float4*)(aptr[l] + k0 + k4);
            As[k4 + 0][r] = v.x;
            As[k4 + 1][r] = v.y;
            As[k4 + 2][r] = v.z;
            As[k4 + 3][r] = v.w;
        }
        // load B tile
        {
            int r  = tid >> 4;
            int c4 = (tid & 15) * 4;
            float4 v = *(const float4*)(B + (size_t)(k0 + r) * HID + n0 + c4);
            *(float4*)&Bs[r][c4] = v;
        }
        __syncthreads();

#pragma unroll
        for (int kk = 0; kk < 16; kk++) {
            float4 a0 = *(const float4*)&As[kk][ty * 8];
            float4 a1 = *(const float4*)&As[kk][ty * 8 + 4];
            float4 b  = *(const float4*)&Bs[kk][tx * 4];
            float aa[8] = {a0.x, a0.y, a0.z, a0.w, a1.x, a1.y, a1.z, a1.w};
            float bb[4] = {b.x, b.y, b.z, b.w};
#pragma unroll
            for (int i = 0; i < 8; i++)
#pragma unroll
                for (int j = 0; j < 4; j++) acc[i][j] += aa[i] * bb[j];
        }
        __syncthreads();
    }

    float bv[4] = {0.f, 0.f, 0.f, 0.f};
    if (bias) {
        float4 b4 = *(const float4*)(bias + n0 + tx * 4);
        bv[0] = b4.x; bv[1] = b4.y; bv[2] = b4.z; bv[3] = b4.w;
    }
#pragma unroll
    for (int i = 0; i < 8; i++) {
        int row = m0 + ty * 8 + i;
        if (row < NMSG) {
            float4 o;
            o.x = acc[i][0] + bv[0];
            o.y = acc[i][1] + bv[1];
            o.z = acc[i][2] + bv[2];
            o.w = acc[i][3] + bv[3];
            *(float4*)(C + (size_t)row * HID + n0 + tx * 4) = o;
        }
    }
}

// ---------------------------------------------------------------------------
// Dual GEMM + fused GRU update:
//   z    = sigmoid(xWz + sum_h @ Uz)
//   preh = tanh  (xWh + sg    @ Uh)
//   hout = ((1-z)*sum_h + z*preh) * mask   (row 0 -> 0)
// ---------------------------------------------------------------------------
__global__ void __launch_bounds__(256)
gru_update(const float* __restrict__ sumh,
           const float* __restrict__ sg,
           const float* __restrict__ Uz,
           const float* __restrict__ Uh,
           const float* __restrict__ xWz,
           const float* __restrict__ xWh,
           float* __restrict__ hout)
{
    __shared__ float As1[16][132];
    __shared__ float As2[16][132];
    __shared__ float Bs1[16][68];
    __shared__ float Bs2[16][68];

    const int m0  = blockIdx.x * 128;
    const int n0  = blockIdx.y * 64;
    const int tid = threadIdx.x;
    const int ty  = tid >> 4;
    const int tx  = tid & 15;

    float acc1[8][4], acc2[8][4];
#pragma unroll
    for (int i = 0; i < 8; i++)
#pragma unroll
        for (int j = 0; j < 4; j++) { acc1[i][j] = 0.f; acc2[i][j] = 0.f; }

    for (int k0 = 0; k0 < HID; k0 += 16) {
#pragma unroll
        for (int l = 0; l < 2; l++) {
            int L  = tid + l * 256;
            int r  = L >> 2;
            int k4 = (L & 3) * 4;
            int row = m0 + r;
            float4 v1 = make_float4(0.f, 0.f, 0.f, 0.f);
            float4 v2 = make_float4(0.f, 0.f, 0.f, 0.f);
            if (row < NMSG) {
                v1 = *(const float4*)(sumh + (size_t)row * HID + k0 + k4);
                v2 = *(const float4*)(sg   + (size_t)row * HID + k0 + k4);
            }
            As1[k4 + 0][r] = v1.x; As1[k4 + 1][r] = v1.y;
            As1[k4 + 2][r] = v1.z; As1[k4 + 3][r] = v1.w;
            As2[k4 + 0][r] = v2.x; As2[k4 + 1][r] = v2.y;
            As2[k4 + 2][r] = v2.z; As2[k4 + 3][r] = v2.w;
        }
        {
            int r  = tid >> 4;
            int c4 = (tid & 15) * 4;
            *(float4*)&Bs1[r][c4] = *(const float4*)(Uz + (size_t)(k0 + r) * HID + n0 + c4);
            *(float4*)&Bs2[r][c4] = *(const float4*)(Uh + (size_t)(k0 + r) * HID + n0 + c4);
        }
        __syncthreads();

#pragma unroll
        for (int kk = 0; kk < 16; kk++) {
            float4 a0 = *(const float4*)&As1[kk][ty * 8];
            float4 a1 = *(const float4*)&As1[kk][ty * 8 + 4];
            float4 c0 = *(const float4*)&As2[kk][ty * 8];
            float4 c1 = *(const float4*)&As2[kk][ty * 8 + 4];
            float4 b1 = *(const float4*)&Bs1[kk][tx * 4];
            float4 b2 = *(const float4*)&Bs2[kk][tx * 4];
            float aa[8] = {a0.x, a0.y, a0.z, a0.w, a1.x, a1.y, a1.z, a1.w};
            float cc[8] = {c0.x, c0.y, c0.z, c0.w, c1.x, c1.y, c1.z, c1.w};
            float bb1[4] = {b1.x, b1.y, b1.z, b1.w};
            float bb2[4] = {b2.x, b2.y, b2.z, b2.w};
#pragma unroll
            for (int i = 0; i < 8; i++)
#pragma unroll
                for (int j = 0; j < 4; j++) {
                    acc1[i][j] += aa[i] * bb1[j];
                    acc2[i][j] += cc[i] * bb2[j];
                }
        }
        __syncthreads();
    }

#pragma unroll
    for (int i = 0; i < 8; i++) {
        int row = m0 + ty * 8 + i;
        if (row < NMSG) {
            size_t off = (size_t)row * HID + n0 + tx * 4;
            float4 s  = *(const float4*)(sumh + off);
            float4 wz = *(const float4*)(xWz + off);
            float4 wh = *(const float4*)(xWh + off);
            float4 o;
            {
                float z = fsigmoid(wz.x + acc1[i][0]);
                float p = ftanh(wh.x + acc2[i][0]);
                o.x = (1.f - z) * s.x + z * p;
            }
            {
                float z = fsigmoid(wz.y + acc1[i][1]);
                float p = ftanh(wh.y + acc2[i][1]);
                o.y = (1.f - z) * s.y + z * p;
            }
            {
                float z = fsigmoid(wz.z + acc1[i][2]);
                float p = ftanh(wh.z + acc2[i][2]);
                o.z = (1.f - z) * s.z + z * p;
            }
            {
                float z = fsigmoid(wz.w + acc1[i][3]);
                float p = ftanh(wh.w + acc2[i][3]);
                o.w = (1.f - z) * s.w + z * p;
            }
            if (row == 0) o = make_float4(0.f, 0.f, 0.f, 0.f);
            *(float4*)(hout + off) = o;
        }
    }
}

// ---------------------------------------------------------------------------
// Gather kernel: per message m:
//   sum_h[m] = sum_d h[n_d]
//   sg[m]    = sum_d sigmoid(r1[m] + hUr[n_d]) * h[n_d]
// 64 threads (float4) per message, 4 messages per block.
// ---------------------------------------------------------------------------
__global__ void __launch_bounds__(256)
gather_kernel(const float* __restrict__ h,
              const float* __restrict__ hUr,
              const float* __restrict__ r1,
              const int* __restrict__ mess_graph,
              float* __restrict__ sumh,
              float* __restrict__ sg)
{
    int m = blockIdx.x * 4 + (threadIdx.x >> 6);
    if (m >= NMSG) return;
    int c = (threadIdx.x & 63) * 4;

    int4 nb = *(const int4*)(mess_graph + (size_t)m * 4);
    int n[4] = {nb.x, nb.y, nb.z, nb.w};

    float4 r1v = *(const float4*)(r1 + (size_t)m * HID + c);
    float4 s = make_float4(0.f, 0.f, 0.f, 0.f);
    float4 g = make_float4(0.f, 0.f, 0.f, 0.f);

#pragma unroll
    for (int d = 0; d < 4; d++) {
        size_t off = (size_t)n[d] * HID + c;
        float4 hv = *(const float4*)(h + off);
        float4 uv = *(const float4*)(hUr + off);
        float r;
        r = fsigmoid(r1v.x + uv.x); s.x += hv.x; g.x += r * hv.x;
        r = fsigmoid(r1v.y + uv.y); s.y += hv.y; g.y += r * hv.y;
        r = fsigmoid(r1v.z + uv.z); s.z += hv.z; g.z += r * hv.z;
        r = fsigmoid(r1v.w + uv.w); s.w += hv.w; g.w += r * hv.w;
    }
    *(float4*)(sumh + (size_t)m * HID + c) = s;
    *(float4*)(sg   + (size_t)m * HID + c) = g;
}

// ---------------------------------------------------------------------------
// Iteration 1 (h=0 shortcut): h = sigmoid(xWz) * tanh(xWh), row 0 -> 0
// ---------------------------------------------------------------------------
__global__ void __launch_bounds__(256)
iter1_kernel(const float* __restrict__ xWz,
             const float* __restrict__ xWh,
             float* __restrict__ h)
{
    size_t idx = (size_t)blockIdx.x * 256 + threadIdx.x;  // float4 index
    const size_t total = (size_t)NMSG * (HID / 4);
    if (idx >= total) return;
    size_t off = idx * 4;
    float4 a = *(const float4*)(xWz + off);
    float4 b = *(const float4*)(xWh + off);
    float4 o;
    o.x = fsigmoid(a.x) * ftanh(b.x);
    o.y = fsigmoid(a.y) * ftanh(b.y);
    o.z = fsigmoid(a.z) * ftanh(b.z);
    o.w = fsigmoid(a.w) * ftanh(b.w);
    if (idx < (HID / 4)) o = make_float4(0.f, 0.f, 0.f, 0.f);  // row 0 mask
    *(float4*)(h + off) = o;
}

// ---------------------------------------------------------------------------
// Epilogue: only the 512 roots matter.
//   v = [emb[fnode[node]], sum_d messages[node_graph[node,d]]]   (512)
//   tree_vecs[b] = relu(v @ Wo + bo)
// ---------------------------------------------------------------------------
__global__ void __launch_bounds__(256)
epilogue_kernel(const int* __restrict__ root_indices,
                const int* __restrict__ fnode,
                const int* __restrict__ node_graph,
                const float* __restrict__ emb,
                const float* __restrict__ messages,
                const float* __restrict__ Wo,
                const float* __restrict__ bo,
                float* __restrict__ out)
{
    __shared__ float v[2 * HID];
    int b = blockIdx.x;
    int t = threadIdx.x;
    int node = root_indices[b];
    v[t] = emb[(size_t)fnode[node] * HID + t];
    float s = 0.f;
#pragma unroll
    for (int d = 0; d < 4; d++)
        s += messages[(size_t)node_graph[(size_t)node * 4 + d] * HID + t];
    v[HID + t] = s;
    __syncthreads();

    float acc = bo[t];
#pragma unroll 4
    for (int k = 0; k < 2 * HID; k++)
        acc += v[k] * Wo[(size_t)k * HID + t];
    out[(size_t)b * HID + t] = fmaxf(acc, 0.f);
}

// ---------------------------------------------------------------------------
extern "C" void kernel_launch(void* const* d_in, const int* in_sizes, int n_in,
                              void* d_out, int out_size)
{
    const int*   fnode        = (const int*)  d_in[0];
    const int*   fmess        = (const int*)  d_in[1];
    const int*   node_graph   = (const int*)  d_in[2];
    const int*   mess_graph   = (const int*)  d_in[3];
    const int*   root_indices = (const int*)  d_in[4];
    const float* emb          = (const float*)d_in[5];
    const float* Wz           = (const float*)d_in[6];
    const float* bz           = (const float*)d_in[7];
    const float* Wr           = (const float*)d_in[8];
    const float* Ur           = (const float*)d_in[9];
    const float* bUr          = (const float*)d_in[10];
    const float* Wh           = (const float*)d_in[11];
    const float* bh           = (const float*)d_in[12];
    const float* Wo           = (const float*)d_in[13];
    const float* bo           = (const float*)d_in[14];

    float* out       = (float*)d_out;
    float* tree_vecs = out;                              // [512, 256]
    float* messages  = out + (size_t)NTREE * HID;        // [200001, 256]

    float *h, *hUr, *r1, *xWz, *xWh, *sumh, *sg;
    cudaGetSymbolAddress((void**)&h,    g_h);
    cudaGetSymbolAddress((void**)&hUr,  g_hUr);
    cudaGetSymbolAddress((void**)&r1,   g_r1);
    cudaGetSymbolAddress((void**)&xWz,  g_xWz);
    cudaGetSymbolAddress((void**)&xWh,  g_xWh);
    cudaGetSymbolAddress((void**)&sumh, g_sumh);
    cudaGetSymbolAddress((void**)&sg,   g_sg);

    const float* Uz = Wz + (size_t)HID * HID;   // rows 256..511 of Wz
    const float* Uh = Wh + (size_t)HID * HID;   // rows 256..511 of Wh

    dim3 ggrid(MPAD / 128, HID / 64);
    const int nblk_rows = (NMSG + 3) / 4;       // gather / iter1 grid

    // Prologue: x = emb[fnode[fmess]];  r1 = x@Wr + bUr;  xWz = x@Wz_top + bz;
    //           xWh = x@Wh_top + bh   (x itself never materialized)
    gemm_single<<<ggrid, 256>>>(nullptr, Wr, bUr, r1,  fmess, fnode, emb, 1);
    gemm_single<<<ggrid, 256>>>(nullptr, Wz, bz,  xWz, fmess, fnode, emb, 1);
    gemm_single<<<ggrid, 256>>>(nullptr, Wh, bh,  xWh, fmess, fnode, emb, 1);

    // GRU iteration 1 (h = 0): pure elementwise
    iter1_kernel<<<nblk_rows, 256>>>(xWz, xWh, h);

    // GRU iterations 2..10
    for (int t = 2; t <= 10; t++) {
        gemm_single<<<ggrid, 256>>>(h, Ur, nullptr, hUr,
                                    nullptr, nullptr, nullptr, 0);
        gather_kernel<<<nblk_rows, 256>>>(h, hUr, r1, mess_graph, sumh, sg);
        float* hout = (t == 10) ? messages : h;
        gru_update<<<ggrid, 256>>>(sumh, sg, Uz, Uh, xWz, xWh, hout);
    }

    // Tree vectors from roots only
    epilogue_kernel<<<NTREE, 256>>>(root_indices, fnode, node_graph,
                                    emb, messages, Wo, bo, tree_vecs);

    (void)in_sizes; (void)n_in; (void)out_size;
}

// round 2
// speedup vs baseline: 1.3260x; 1.3260x over previous
#include <cuda_runtime.h>
#include <cstdint>
#include <cstddef>

#define HID   256
#define NMSG  200001
#define MPAD  200064   // NMSG rounded up to multiple of 128
#define NTREE 512

// ---------------- scratch (device globals: no allocation allowed) ----------
__device__ float g_h  [(size_t)MPAD * HID];
__device__ float g_hUr[(size_t)MPAD * HID];
__device__ float g_hUz[(size_t)MPAD * HID];
__device__ float g_r1 [(size_t)MPAD * HID];   // x@Wr + bUr
__device__ float g_xWz[(size_t)MPAD * HID];   // x@Wz_top + bz
__device__ float g_xWh[(size_t)MPAD * HID];   // x@Wh_top + bh
__device__ float g_sg [(size_t)MPAD * HID];   // sum(r * h_nei)
__device__ float g_a  [(size_t)MPAD * HID];   // (1-z) * sum_h
__device__ float g_z  [(size_t)MPAD * HID];   // z gate

__device__ __forceinline__ float fsigmoid(float x) {
    return 1.0f / (1.0f + __expf(-x));
}
__device__ __forceinline__ float ftanh(float x) {
    x = fminf(fmaxf(x, -15.0f), 15.0f);
    float e = __expf(2.0f * x);
    return (e - 1.0f) / (e + 1.0f);
}
__device__ __forceinline__ uint32_t f2tf(float f) {
    uint32_t u;
    asm("cvt.rna.tf32.f32 %0, %1;" : "=r"(u) : "f"(f));
    return u;
}
__device__ __forceinline__ void mma8(float c[4], const uint32_t a[4], const uint32_t b[2]) {
    asm volatile(
        "mma.sync.aligned.m16n8k8.row.col.f32.tf32.tf32.f32 "
        "{%0,%1,%2,%3}, {%4,%5,%6,%7}, {%8,%9}, {%0,%1,%2,%3};"
        : "+f"(c[0]), "+f"(c[1]), "+f"(c[2]), "+f"(c[3])
        : "r"(a[0]), "r"(a[1]), "r"(a[2]), "r"(a[3]),
          "r"(b[0]), "r"(b[1]));
}

// ---------------------------------------------------------------------------
// tf32 tensor-core GEMM: up to 3 outputs sharing the A operand.
//   C_i[M x 256] = A[M x 256] @ B_i[256 x 256] (+ bias_i)
// GATHER: A row r = emb[fnode[fmess[r]]]
// FINAL (NB==1): C = ea + ez * tanh(exWh + A@B0), row 0 forced to 0
// BM=128, BN=64, BK=32, 256 threads (8 warps in 4x2), warp tile 32x32.
// ---------------------------------------------------------------------------
template<int NB, bool GATHER, bool FINAL>
__global__ void __launch_bounds__(256)
gemm_tf32(const float* __restrict__ A,
          const float* __restrict__ B0, const float* __restrict__ B1,
          const float* __restrict__ B2,
          const float* __restrict__ bias0, const float* __restrict__ bias1,
          const float* __restrict__ bias2,
          float* __restrict__ C0, float* __restrict__ C1,
          float* __restrict__ C2,
          const int* __restrict__ fmess, const int* __restrict__ fnode,
          const float* __restrict__ emb,
          const float* __restrict__ ea, const float* __restrict__ ez,
          const float* __restrict__ exWh)
{
    __shared__ __align__(16) uint32_t As[128][36];      // [m][k], pad 36
    __shared__ __align__(16) uint32_t Bs[NB][32][72];   // [k][n], pad 72

    const int m0  = blockIdx.x * 128;
    const int n0  = blockIdx.y * 64;
    const int tid = threadIdx.x;
    const int lane = tid & 31, w = tid >> 5;
    const int wm = w >> 1, wn = w & 1;            // 4x2 warp grid
    const int g  = lane >> 2, tig = lane & 3;

    // A row pointers: 4 float4 loads per thread, row fixed across k-iterations
    const float* aptr[4];
    bool aval[4];
#pragma unroll
    for (int l = 0; l < 4; l++) {
        int idx = tid + l * 256;
        int r   = idx >> 3;             // 8 float4 per row (32 floats)
        int row = m0 + r;
        aval[l] = (row < NMSG);
        if (aval[l]) {
            if (GATHER) aptr[l] = emb + (size_t)fnode[fmess[row]] * HID;
            else        aptr[l] = A + (size_t)row * HID;
        } else {
            aptr[l] = GATHER ? emb : A;
        }
    }

    float c[NB][2][4][4];
#pragma unroll
    for (int nb = 0; nb < NB; nb++)
#pragma unroll
        for (int mi = 0; mi < 2; mi++)
#pragma unroll
            for (int ni = 0; ni < 4; ni++)
#pragma unroll
                for (int q = 0; q < 4; q++) c[nb][mi][ni][q] = 0.0f;

    const float* Bp[3] = {B0, B1, B2};

    for (int k0 = 0; k0 < HID; k0 += 32) {
        // stage A tile (convert to tf32)
#pragma unroll
        for (int l = 0; l < 4; l++) {
            if (aval[l]) {
                int idx = tid + l * 256;
                int r = idx >> 3, k4 = (idx & 7) * 4;
                float4 v = *(const float4*)(aptr[l] + k0 + k4);
                uint4 u = make_uint4(f2tf(v.x), f2tf(v.y), f2tf(v.z), f2tf(v.w));
                *(uint4*)&As[r][k4] = u;
            }
        }
        // stage B tiles
#pragma unroll
        for (int nb = 0; nb < NB; nb++) {
#pragma unroll
            for (int l = 0; l < 2; l++) {
                int idx = tid + l * 256;
                int r = idx >> 4, c4 = (idx & 15) * 4;   // 16 float4 per row
                float4 v = *(const float4*)(Bp[nb] + (size_t)(k0 + r) * HID + n0 + c4);
                uint4 u = make_uint4(f2tf(v.x), f2tf(v.y), f2tf(v.z), f2tf(v.w));
                *(uint4*)&Bs[nb][r][c4] = u;
            }
        }
        __syncthreads();

#pragma unroll
        for (int ks = 0; ks < 4; ks++) {
            int kk = ks * 8;
            uint32_t afr[2][4];
#pragma unroll
            for (int mi = 0; mi < 2; mi++) {
                int rb = wm * 32 + mi * 16;
                afr[mi][0] = As[rb + g    ][kk + tig    ];
                afr[mi][1] = As[rb + g + 8][kk + tig    ];
                afr[mi][2] = As[rb + g    ][kk + tig + 4];
                afr[mi][3] = As[rb + g + 8][kk + tig + 4];
            }
#pragma unroll
            for (int nb = 0; nb < NB; nb++) {
#pragma unroll
                for (int ni = 0; ni < 4; ni++) {
                    int col = wn * 32 + ni * 8 + g;
                    uint32_t bfr[2];
                    bfr[0] = Bs[nb][kk + tig    ][col];
                    bfr[1] = Bs[nb][kk + tig + 4][col];
                    mma8(c[nb][0][ni], afr[0], bfr);
                    mma8(c[nb][1][ni], afr[1], bfr);
                }
            }
        }
        __syncthreads();
    }

    // Epilogue
    const float* biasp[3] = {bias0, bias1, bias2};
    float* Cp[3] = {C0, C1, C2};
#pragma unroll
    for (int nb = 0; nb < NB; nb++) {
#pragma unroll
        for (int ni = 0; ni < 4; ni++) {
            int col = n0 + wn * 32 + ni * 8 + tig * 2;
            float bvx = 0.f, bvy = 0.f;
            if (!FINAL && biasp[nb]) {
                float2 b2 = *(const float2*)(biasp[nb] + col);
                bvx = b2.x; bvy = b2.y;
            }
#pragma unroll
            for (int mi = 0; mi < 2; mi++) {
#pragma unroll
                for (int hh = 0; hh < 2; hh++) {     // hh=0 -> c0/c1, hh=1 -> c2/c3
                    int row = m0 + wm * 32 + mi * 16 + g + hh * 8;
                    if (row < NMSG) {
                        float v0 = c[nb][mi][ni][hh * 2 + 0];
                        float v1 = c[nb][mi][ni][hh * 2 + 1];
                        size_t off = (size_t)row * HID + col;
                        float2 o;
                        if (FINAL) {
                            float2 av = *(const float2*)(ea   + off);
                            float2 zv = *(const float2*)(ez   + off);
                            float2 wv = *(const float2*)(exWh + off);
                            o.x = av.x + zv.x * ftanh(wv.x + v0);
                            o.y = av.y + zv.y * ftanh(wv.y + v1);
                            if (row == 0) { o.x = 0.f; o.y = 0.f; }
                        } else {
                            o.x = v0 + bvx;
                            o.y = v1 + bvy;
                        }
                        *(float2*)(Cp[nb] + off) = o;
                    }
                }
            }
        }
    }
}

// ---------------------------------------------------------------------------
// Gather kernel. Per message m:
//   sum_h = sum_d h[n_d]
//   sg    = sum_d sigmoid(r1[m] + hUr[n_d]) * h[n_d]
//   z     = sigmoid(xWz[m] + sum_d hUz[n_d])
// outputs: sg, a = (1-z)*sum_h, z
// ---------------------------------------------------------------------------
__global__ void __launch_bounds__(256)
gather2(const float* __restrict__ h,
        const float* __restrict__ hUr,
        const float* __restrict__ hUz,
        const float* __restrict__ r1,
        const float* __restrict__ xWz,
        const int* __restrict__ mess_graph,
        float* __restrict__ sg,
        float* __restrict__ aout,
        float* __restrict__ zout)
{
    int m = blockIdx.x * 4 + (threadIdx.x >> 6);
    if (m >= NMSG) return;
    int cc = (threadIdx.x & 63) * 4;

    int4 nb = *(const int4*)(mess_graph + (size_t)m * 4);
    int n[4] = {nb.x, nb.y, nb.z, nb.w};

    size_t moff = (size_t)m * HID + cc;
    float4 r1v = *(const float4*)(r1 + moff);
    float4 s = make_float4(0.f, 0.f, 0.f, 0.f);
    float4 gg = make_float4(0.f, 0.f, 0.f, 0.f);
    float4 u = make_float4(0.f, 0.f, 0.f, 0.f);

#pragma unroll
    for (int d = 0; d < 4; d++) {
        size_t off = (size_t)n[d] * HID + cc;
        float4 hv = *(const float4*)(h   + off);
        float4 rv = *(const float4*)(hUr + off);
        float4 zv = *(const float4*)(hUz + off);
        float r;
        r = fsigmoid(r1v.x + rv.x); s.x += hv.x; gg.x += r * hv.x; u.x += zv.x;
        r = fsigmoid(r1v.y + rv.y); s.y += hv.y; gg.y += r * hv.y; u.y += zv.y;
        r = fsigmoid(r1v.z + rv.z); s.z += hv.z; gg.z += r * hv.z; u.z += zv.z;
        r = fsigmoid(r1v.w + rv.w); s.w += hv.w; gg.w += r * hv.w; u.w += zv.w;
    }
    float4 xz = *(const float4*)(xWz + moff);
    float4 z;
    z.x = fsigmoid(xz.x + u.x);
    z.y = fsigmoid(xz.y + u.y);
    z.z = fsigmoid(xz.z + u.z);
    z.w = fsigmoid(xz.w + u.w);

    *(float4*)(sg + moff) = gg;
    float4 av;
    av.x = (1.f - z.x) * s.x; av.y = (1.f - z.y) * s.y;
    av.z = (1.f - z.z) * s.z; av.w = (1.f - z.w) * s.w;
    *(float4*)(aout + moff) = av;
    *(float4*)(zout + moff) = z;
}

// ---------------------------------------------------------------------------
// Iteration 1 (h=0 shortcut): h = sigmoid(xWz) * tanh(xWh), row 0 -> 0
// ---------------------------------------------------------------------------
__global__ void __launch_bounds__(256)
iter1_kernel(const float* __restrict__ xWz,
             const float* __restrict__ xWh,
             float* __restrict__ h)
{
    size_t idx = (size_t)blockIdx.x * 256 + threadIdx.x;  // float4 index
    const size_t total = (size_t)NMSG * (HID / 4);
    if (idx >= total) return;
    size_t off = idx * 4;
    float4 a = *(const float4*)(xWz + off);
    float4 b = *(const float4*)(xWh + off);
    float4 o;
    o.x = fsigmoid(a.x) * ftanh(b.x);
    o.y = fsigmoid(a.y) * ftanh(b.y);
    o.z = fsigmoid(a.z) * ftanh(b.z);
    o.w = fsigmoid(a.w) * ftanh(b.w);
    if (idx < (HID / 4)) o = make_float4(0.f, 0.f, 0.f, 0.f);  // row 0 mask
    *(float4*)(h + off) = o;
}

// ---------------------------------------------------------------------------
// Epilogue: only the 512 roots matter.
// ---------------------------------------------------------------------------
__global__ void __launch_bounds__(256)
epilogue_kernel(const int* __restrict__ root_indices,
                const int* __restrict__ fnode,
                const int* __restrict__ node_graph,
                const float* __restrict__ emb,
                const float* __restrict__ messages,
                const float* __restrict__ Wo,
                const float* __restrict__ bo,
                float* __restrict__ out)
{
    __shared__ float v[2 * HID];
    int b = blockIdx.x;
    int t = threadIdx.x;
    int node = root_indices[b];
    v[t] = emb[(size_t)fnode[node] * HID + t];
    float s = 0.f;
#pragma unroll
    for (int d = 0; d < 4; d++)
        s += messages[(size_t)node_graph[(size_t)node * 4 + d] * HID + t];
    v[HID + t] = s;
    __syncthreads();

    float acc = bo[t];
#pragma unroll 4
    for (int k = 0; k < 2 * HID; k++)
        acc += v[k] * Wo[(size_t)k * HID + t];
    out[(size_t)b * HID + t] = fmaxf(acc, 0.f);
}

// ---------------------------------------------------------------------------
extern "C" void kernel_launch(void* const* d_in, const int* in_sizes, int n_in,
                              void* d_out, int out_size)
{
    const int*   fnode        = (const int*)  d_in[0];
    const int*   fmess        = (const int*)  d_in[1];
    const int*   node_graph   = (const int*)  d_in[2];
    const int*   mess_graph   = (const int*)  d_in[3];
    const int*   root_indices = (const int*)  d_in[4];
    const float* emb          = (const float*)d_in[5];
    const float* Wz           = (const float*)d_in[6];
    const float* bz           = (const float*)d_in[7];
    const float* Wr           = (const float*)d_in[8];
    const float* Ur           = (const float*)d_in[9];
    const float* bUr          = (const float*)d_in[10];
    const float* Wh           = (const float*)d_in[11];
    const float* bh           = (const float*)d_in[12];
    const float* Wo           = (const float*)d_in[13];
    const float* bo           = (const float*)d_in[14];

    float* out       = (float*)d_out;
    float* tree_vecs = out;                          // [512, 256]
    float* messages  = out + (size_t)NTREE * HID;    // [200001, 256]

    float *h, *hUr, *hUz, *r1, *xWz, *xWh, *sg, *a, *z;
    cudaGetSymbolAddress((void**)&h,   g_h);
    cudaGetSymbolAddress((void**)&hUr, g_hUr);
    cudaGetSymbolAddress((void**)&hUz, g_hUz);
    cudaGetSymbolAddress((void**)&r1,  g_r1);
    cudaGetSymbolAddress((void**)&xWz, g_xWz);
    cudaGetSymbolAddress((void**)&xWh, g_xWh);
    cudaGetSymbolAddress((void**)&sg,  g_sg);
    cudaGetSymbolAddress((void**)&a,   g_a);
    cudaGetSymbolAddress((void**)&z,   g_z);

    const float* Uz = Wz + (size_t)HID * HID;   // rows 256..511 of Wz
    const float* Uh = Wh + (size_t)HID * HID;   // rows 256..511 of Wh

    dim3 ggrid(MPAD / 128, HID / 64);
    const int nblk_msg = (NMSG + 3) / 4;

    // Prologue (one pass over gathered emb rows):
    //   r1 = x@Wr + bUr; xWz = x@Wz_top + bz; xWh = x@Wh_top + bh
    gemm_tf32<3, true, false><<<ggrid, 256>>>(
        nullptr, Wr, Wz, Wh, bUr, bz, bh, r1, xWz, xWh,
        fmess, fnode, emb, nullptr, nullptr, nullptr);

    // GRU iteration 1 (h = 0): pure elementwise
    iter1_kernel<<<nblk_msg, 256>>>(xWz, xWh, h);

    // GRU iterations 2..10
    for (int t = 2; t <= 10; t++) {
        // hUr = h@Ur, hUz = h@Uz (shared A)
        gemm_tf32<2, false, false><<<ggrid, 256>>>(
            h, Ur, Uz, nullptr, nullptr, nullptr, nullptr,
            hUr, hUz, nullptr,
            nullptr, nullptr, nullptr, nullptr, nullptr, nullptr);
        // sg, a=(1-z)sum_h, z
        gather2<<<nblk_msg, 256>>>(h, hUr, hUz, r1, xWz, mess_graph, sg, a, z);
        // h = a + z * tanh(xWh + sg@Uh), row 0 -> 0
        float* hout = (t == 10) ? messages : h;
        gemm_tf32<1, false, true><<<ggrid, 256>>>(
            sg, Uh, nullptr, nullptr, nullptr, nullptr, nullptr,
            hout, nullptr, nullptr,
            nullptr, nullptr, nullptr, a, z, xWh);
    }

    // Tree vectors from roots only
    epilogue_kernel<<<NTREE, 256>>>(root_indices, fnode, node_graph,
                                    emb, messages, Wo, bo, tree_vecs);

    (void)in_sizes; (void)n_in; (void)out_size;
}